// round 5
// baseline (speedup 1.0000x reference)
#include <cuda_runtime.h>

// ---------------- problem constants ----------------
#define O_    2
#define Z_    8
#define OY_   1024
#define P_    8
#define N_    256
#define NB_   32
#define NF    65536          // N_*N_
#define CP    257            // padded pitch (in float2) for column tiles
#define TWO_PI 6.28318530717958647692f

// Bank-conflict-killing address swizzle for the 256-pt FFT buffers.
// Bijection on [0,256): XORs bits 4-5 into bits 2-3 and bits 6-7 into bits 0-1.
// Makes every LDS/STS phase of all 4 Stockham stages (and the strided caller
// accesses lane+32t) hit 16 distinct banks per half-warp.
#define SW(a) ((a) ^ ((((a) >> 2) & 12)) ^ ((((a) >> 4) & 3)))

// ---------------- static device scratch ----------------
__device__ float2 g_tw[N_];                       // e^{+2*pi*i*k/256}
__device__ int    g_cy[NB_], g_cx[NB_];
__device__ float  g_sy[NB_], g_sx[NB_];
__device__ float2 g_probeF[(size_t)P_ * NF];                  // fft2(probe)
__device__ float2 g_probes[(size_t)NB_ * P_ * NF];            // shifted probes (spatial)
__device__ float2 g_bufA[(size_t)NB_ * O_ * P_ * NF];         // rowsA out / cols in
__device__ float2 g_bufB[(size_t)NB_ * O_ * P_ * NF];         // colsH out / rowsA in

// ---------------- complex helpers ----------------
__device__ __forceinline__ float2 cadd(float2 a, float2 b){ return make_float2(a.x+b.x, a.y+b.y); }
__device__ __forceinline__ float2 csub(float2 a, float2 b){ return make_float2(a.x-b.x, a.y-b.y); }
__device__ __forceinline__ float2 cmul(float2 a, float2 b){ return make_float2(a.x*b.x - a.y*b.y, a.x*b.y + a.y*b.x); }

// ---------------- warp-private 256-pt Stockham radix-4 FFT (swizzled) ----------------
// buf: 256 float2 region touched only by this warp; ALL indices pass through SW().
// DIR = -1 forward (e^{-i}), +1 inverse (unscaled).
// In-place safe: all 64 butterflies are read into registers (8 pts/thread)
// before any write, with __syncwarp between the phases.
template<int DIR>
__device__ __forceinline__ void warp_fft256(float2* buf, int lane, const float2* tw){
    int s = 1;
    #pragma unroll
    for (int st = 0; st < 4; st++){
        int m = 64 / s;
        float2 v[2][4];
        int pb[2], qb[2];
        #pragma unroll
        for (int h = 0; h < 2; h++){
            int u = lane + 32*h;
            int p = u / s;
            int q = u - p*s;
            pb[h] = p; qb[h] = q;
            #pragma unroll
            for (int k = 0; k < 4; k++)
                v[h][k] = buf[SW(q + s*(p + k*m))];
        }
        __syncwarp();
        #pragma unroll
        for (int h = 0; h < 2; h++){
            int p = pb[h], q = qb[h];
            float2 a = v[h][0], b = v[h][1], c = v[h][2], d = v[h][3];
            float2 apc = cadd(a,c), amc = csub(a,c);
            float2 bpd = cadd(b,d), bmd = csub(b,d);
            // DIR * j * (b-d)
            float2 jb = make_float2(-(float)DIR * bmd.y, (float)DIR * bmd.x);
            float2 y0 = cadd(apc, bpd);
            float2 t1 = cadd(amc, jb);
            float2 y2 = csub(apc, bpd);
            float2 t3 = csub(amc, jb);
            int k1 = p*s;
            float2 w1 = tw[k1];     w1.y *= (float)DIR;
            float2 w2 = tw[2*k1];   w2.y *= (float)DIR;
            float2 w3 = tw[3*k1];   w3.y *= (float)DIR;
            int ob = q + s*4*p;
            buf[SW(ob      )] = y0;
            buf[SW(ob +   s)] = cmul(w1, t1);
            buf[SW(ob + 2*s)] = cmul(w2, y2);
            buf[SW(ob + 3*s)] = cmul(w3, t3);
        }
        __syncwarp();
        s *= 4;
    }
}

// ---------------- setup: twiddles + index resolution ----------------
__global__ void k_setup(const float* __restrict__ shifts,
                        const int*   __restrict__ crop,
                        const void*  __restrict__ idxraw){
    int t = threadIdx.x;
    if (t < N_){
        double ang = 2.0 * 3.14159265358979323846 * (double)t / (double)N_;
        g_tw[t] = make_float2((float)cos(ang), (float)sin(ang));
    }
    if (t == 0){
        // dtype detection: safe 128B read either way (NB_=32 int32 words)
        const int* w = (const int*)idxraw;
        int orr = 0;
        for (int k = 1; k < NB_; k += 2) orr |= w[k];
        bool is64 = (orr == 0);
        for (int b = 0; b < NB_; b++){
            int id = is64 ? (int)(((const long long*)idxraw)[b]) : w[b];
            g_cy[b] = crop[2*id];
            g_cx[b] = crop[2*id + 1];
            g_sy[b] = shifts[2*id];
            g_sx[b] = shifts[2*id + 1];
        }
    }
}

// ---------------- probe forward FFT: rows ----------------
__global__ void k_probe_rows(const float* __restrict__ pr, const float* __restrict__ pi){
    // grid P_*32, 256 threads; warp per row, 8 rows per CTA
    int blk = blockIdx.x, rblk = blk & 31, p = blk >> 5;
    int w = threadIdx.x >> 5, lane = threadIdx.x & 31;
    int y = rblk*8 + w;
    __shared__ float2 fb[8][N_];
    __shared__ float2 tw[N_];
    for (int i = threadIdx.x; i < N_; i += 256) tw[i] = g_tw[i];
    __syncthreads();
    size_t base = ((size_t)p * N_ + y) * N_;
    for (int xx = lane; xx < N_; xx += 32)
        fb[w][SW(xx)] = make_float2(pr[base+xx], pi[base+xx]);
    __syncwarp();
    warp_fft256<-1>(fb[w], lane, tw);
    for (int xx = lane; xx < N_; xx += 32)
        g_probeF[base+xx] = fb[w][SW(xx)];
}

// ---------------- probe forward FFT: cols (in place) ----------------
__global__ void k_probe_cols(){
    // grid P_*16, 512 threads; warp per column, 16-col tile
    int blk = blockIdx.x, tile = blk & 15, p = blk >> 4;
    int xg0 = tile*16;
    int w = threadIdx.x >> 5, lane = threadIdx.x & 31;
    __shared__ float2 sh[16*CP];
    __shared__ float2 tw[N_];
    for (int i = threadIdx.x; i < N_; i += 512) tw[i] = g_tw[i];
    float2* fld = g_probeF + (size_t)p * NF;
    for (int i = threadIdx.x; i < 4096; i += 512){
        int yy = i >> 4, xx = i & 15;
        sh[xx*CP + SW(yy)] = fld[(size_t)yy*N_ + xg0 + xx];
    }
    __syncthreads();
    warp_fft256<-1>(sh + w*CP, lane, tw);
    __syncthreads();
    for (int i = threadIdx.x; i < 4096; i += 512){
        int yy = i >> 4, xx = i & 15;
        fld[(size_t)yy*N_ + xg0 + xx] = sh[xx*CP + SW(yy)];
    }
}

// ---------------- shifted probes: ramp multiply + row inverse FFT ----------------
__global__ void k_probes_rows(){
    // grid NB_*P_*32, 256 threads
    int blk = blockIdx.x, rblk = blk & 31, bp = blk >> 5;
    int p = bp & 7, b = bp >> 3;
    int w = threadIdx.x >> 5, lane = threadIdx.x & 31;
    int y = rblk*8 + w;
    __shared__ float2 fb[8][N_];
    __shared__ float2 tw[N_];
    for (int i = threadIdx.x; i < N_; i += 256) tw[i] = g_tw[i];
    __syncthreads();
    float sy = g_sy[b], sx = g_sx[b];
    float angy = -(TWO_PI / N_) * sy * (float)y;
    size_t base = ((size_t)p * N_ + y) * N_;
    const float invn = 1.0f / N_;
    for (int xx = lane; xx < N_; xx += 32){
        float ang = angy - (TWO_PI / N_) * sx * (float)xx;
        float sn, cs;
        sincosf(ang, &sn, &cs);                 // large args -> accurate version
        float2 r = make_float2(cs*invn, sn*invn); // fold row-inverse 1/N
        fb[w][SW(xx)] = cmul(g_probeF[base+xx], r);
    }
    __syncwarp();
    warp_fft256<+1>(fb[w], lane, tw);
    float2* dst = g_probes + ((size_t)b*P_ + p) * NF + (size_t)y * N_;
    for (int xx = lane; xx < N_; xx += 32) dst[xx] = fb[w][SW(xx)];
}

// ---------------- shifted probes: col inverse FFT (in place, scaled) ----------------
__global__ void k_cols_inv(){
    // grid NB_*P_*16, 512 threads
    int blk = blockIdx.x, tile = blk & 15, f = blk >> 4;
    int xg0 = tile*16;
    int w = threadIdx.x >> 5, lane = threadIdx.x & 31;
    __shared__ float2 sh[16*CP];
    __shared__ float2 tw[N_];
    for (int i = threadIdx.x; i < N_; i += 512) tw[i] = g_tw[i];
    float2* fld = g_probes + (size_t)f * NF;
    for (int i = threadIdx.x; i < 4096; i += 512){
        int yy = i >> 4, xx = i & 15;
        sh[xx*CP + SW(yy)] = fld[(size_t)yy*N_ + xg0 + xx];
    }
    __syncthreads();
    warp_fft256<+1>(sh + w*CP, lane, tw);
    __syncthreads();
    const float invn = 1.0f / N_;
    for (int i = threadIdx.x; i < 4096; i += 512){
        int yy = i >> 4, xx = i & 15;
        float2 v = sh[xx*CP + SW(yy)];
        fld[(size_t)yy*N_ + xg0 + xx] = make_float2(v.x*invn, v.y*invn);
    }
}

// ---------------- rows pass A: [row-IFFT] -> x obj[z] -> row-FFT, writes pp ----------------
__global__ void k_rows_A(const float* __restrict__ obja, const float* __restrict__ objp,
                         float* __restrict__ pp_out, int z){
    // grid NB_*O_*32, 256 threads; warp per row, loops p (obj shared across P)
    int blk = blockIdx.x, rblk = blk & 31, bo = blk >> 5;
    int o = bo & 1, b = bo >> 1;
    int w = threadIdx.x >> 5, lane = threadIdx.x & 31;
    int y = rblk*8 + w;
    __shared__ float2 objsh[8][N_];
    __shared__ float2 fb[8][N_];
    __shared__ float2 tw[N_];
    for (int i = threadIdx.x; i < N_; i += 256) tw[i] = g_tw[i];

    int cy = g_cy[b], cx = g_cx[b];
    size_t obase = (((size_t)(o*Z_ + z)) * OY_ + (size_t)(cy + y)) * OY_ + cx;
    float scale = (z == 0) ? 1.0f : (1.0f / N_);   // fold row-IFFT 1/N into obj
    size_t ppbase = ((((size_t)b*O_ + o)*Z_ + z) * N_ + y) * (size_t)N_;
    for (int xx = lane; xx < N_; xx += 32){
        float A  = obja[obase + xx];
        float ph = objp[obase + xx];
        float sn, cs;
        __sincosf(ph, &sn, &cs);                   // |ph| small -> fast intrinsic OK
        objsh[w][SW(xx)] = make_float2(A*cs*scale, A*sn*scale);
        pp_out[ppbase + xx] = ph;
    }
    __syncthreads();

    for (int p = 0; p < P_; p++){
        const float2* src = (z == 0)
            ? (g_probes + ((size_t)b*P_ + p) * NF + (size_t)y * N_)
            : (g_bufB  + ((size_t)bo*P_ + p) * NF + (size_t)y * N_);
        for (int xx = lane; xx < N_; xx += 32) fb[w][SW(xx)] = src[xx];
        __syncwarp();
        if (z) warp_fft256<+1>(fb[w], lane, tw);
        for (int xx = lane; xx < N_; xx += 32){
            int sx_ = SW(xx);
            fb[w][sx_] = cmul(fb[w][sx_], objsh[w][sx_]);
        }
        __syncwarp();
        warp_fft256<-1>(fb[w], lane, tw);
        float2* dst = g_bufA + ((size_t)bo*P_ + p) * NF + (size_t)y * N_;
        for (int xx = lane; xx < N_; xx += 32) dst[xx] = fb[w][SW(xx)];
        __syncwarp();
    }
}

// ---------------- cols pass B: col-FFT -> x H -> col-IFFT ----------------
__global__ void k_cols_H(const float* __restrict__ Hr, const float* __restrict__ Hi){
    // grid NB_*O_*P_*16, 512 threads
    int blk = blockIdx.x, tile = blk & 15, f = blk >> 4;
    int xg0 = tile*16;
    int w = threadIdx.x >> 5, lane = threadIdx.x & 31;
    __shared__ float2 sh[16*CP];
    __shared__ float2 tw[N_];
    for (int i = threadIdx.x; i < N_; i += 512) tw[i] = g_tw[i];
    const float2* s = g_bufA + (size_t)f * NF;
    for (int i = threadIdx.x; i < 4096; i += 512){
        int yy = i >> 4, xx = i & 15;
        sh[xx*CP + SW(yy)] = s[(size_t)yy*N_ + xg0 + xx];
    }
    __syncthreads();
    float2* cb = sh + w*CP;
    warp_fft256<-1>(cb, lane, tw);
    const float invn = 1.0f / N_;                  // fold col-IFFT 1/N into H
    int xg = xg0 + w;
    for (int yy = lane; yy < N_; yy += 32){
        float2 h = make_float2(Hr[yy*N_ + xg] * invn, Hi[yy*N_ + xg] * invn);
        int sy_ = SW(yy);
        cb[sy_] = cmul(cb[sy_], h);
    }
    __syncwarp();
    warp_fft256<+1>(cb, lane, tw);
    __syncthreads();
    float2* d = g_bufB + (size_t)f * NF;
    for (int i = threadIdx.x; i < 4096; i += 512){
        int yy = i >> 4, xx = i & 15;
        d[(size_t)yy*N_ + xg0 + xx] = sh[xx*CP + SW(yy)];
    }
}

// ---------------- final: col-FFT -> weighted |.|^2 accumulation -> dp (fftshift) ----------------
__global__ void k_cols_final(const float* __restrict__ occu, float* __restrict__ dp){
    // grid NB_*16, 512 threads; accumulates over o (2) and p (8) per tile
    int blk = blockIdx.x, tile = blk & 15, b = blk >> 4;
    int xg0 = tile*16;
    int w = threadIdx.x >> 5, lane = threadIdx.x & 31;
    __shared__ float2 sh[16*CP];
    __shared__ float2 tw[N_];
    for (int i = threadIdx.x; i < N_; i += 512) tw[i] = g_tw[i];
    float acc[8];
    #pragma unroll
    for (int k = 0; k < 8; k++) acc[k] = 0.0f;

    for (int o = 0; o < O_; o++){
        float wt = occu[o];
        for (int p = 0; p < P_; p++){
            const float2* s = g_bufA + ((size_t)((b*O_ + o)*P_ + p)) * NF;
            __syncthreads();                        // protect sh from previous iteration
            for (int i = threadIdx.x; i < 4096; i += 512){
                int yy = i >> 4, xx = i & 15;
                sh[xx*CP + SW(yy)] = s[(size_t)yy*N_ + xg0 + xx];
            }
            __syncthreads();
            float2* cb = sh + w*CP;
            warp_fft256<-1>(cb, lane, tw);
            #pragma unroll
            for (int k = 0; k < 8; k++){
                float2 v = cb[SW(lane + 32*k)];
                acc[k] += wt * (v.x*v.x + v.y*v.y);
            }
        }
    }
    // stage accumulators through shared for coalesced, fftshifted writes
    __syncthreads();
    float* shf = (float*)sh;
    #pragma unroll
    for (int k = 0; k < 8; k++) shf[w*CP*2 + lane + 32*k] = acc[k];
    __syncthreads();
    int xs0 = (xg0 + 128) & 255;
    for (int i = threadIdx.x; i < 4096; i += 512){
        int yy = i >> 4, xx = i & 15;
        int ys = (yy + 128) & 255;
        dp[(size_t)b*NF + (size_t)ys*N_ + xs0 + xx] = shf[xx*CP*2 + yy];
    }
}

// ---------------- launch ----------------
extern "C" void kernel_launch(void* const* d_in, const int* in_sizes, int n_in,
                              void* d_out, int out_size){
    const float* obja   = (const float*)d_in[0];
    const float* objp   = (const float*)d_in[1];
    const float* pr     = (const float*)d_in[2];
    const float* pi     = (const float*)d_in[3];
    const float* Hr     = (const float*)d_in[4];
    const float* Hi     = (const float*)d_in[5];
    const float* occu   = (const float*)d_in[6];
    const float* shifts = (const float*)d_in[7];
    const int*   crop   = (const int*)d_in[8];
    const void*  idx    = d_in[9];

    float* dp = (float*)d_out;                    // (NB, 256, 256)
    float* pp = dp + (size_t)NB_ * NF;            // (NB, O, Z, 256, 256)

    k_setup<<<1, 256>>>(shifts, crop, idx);
    k_probe_rows<<<P_*32, 256>>>(pr, pi);
    k_probe_cols<<<P_*16, 512>>>();
    k_probes_rows<<<NB_*P_*32, 256>>>();
    k_cols_inv<<<NB_*P_*16, 512>>>();

    k_rows_A<<<NB_*O_*32, 256>>>(obja, objp, pp, 0);
    for (int z = 0; z < Z_ - 1; z++){
        k_cols_H<<<NB_*O_*P_*16, 512>>>(Hr, Hi);
        k_rows_A<<<NB_*O_*32, 256>>>(obja, objp, pp, z + 1);
    }
    k_cols_final<<<NB_*16, 512>>>(occu, dp);
}

// round 6
// speedup vs baseline: 2.3896x; 2.3896x over previous
#include <cuda_runtime.h>

// ---------------- problem constants ----------------
#define O_    2
#define Z_    8
#define OY_   1024
#define P_    8
#define N_    256
#define NB_   32
#define NF    65536
#define TWO_PI 6.28318530717958647692f
#define PI_F  3.14159265358979323846f

// XOR-swizzled column-tile addressing (8 columns x 256 rows, float2).
// Conflict-free for row-chunk staging AND per-warp column access.
#define TADDR(my,j) ((((my) << 3)) | ((j) ^ (((my) >> 2) & 7)))

// ---------------- static device scratch ----------------
__device__ int    g_cy[NB_], g_cx[NB_];
__device__ float  g_sy[NB_], g_sx[NB_];
__device__ float2 g_Ht[(size_t)NF];                    // H permuted both axes, /256 folded
__device__ float2 g_probeF[(size_t)P_ * NF];           // fft2(probe), digit-permuted axes
__device__ float2 g_probes[(size_t)NB_ * P_ * NF];     // shifted probes, spatial (natural)
__device__ float2 g_bufA[(size_t)NB_ * O_ * P_ * NF];  // rowsA out (x-permuted, y-natural)
__device__ float2 g_bufB[(size_t)NB_ * O_ * P_ * NF];  // colsH out (x-permuted, y-natural)

// ---------------- complex helpers ----------------
__device__ __forceinline__ float2 cadd(float2 a, float2 b){ return make_float2(a.x+b.x, a.y+b.y); }
__device__ __forceinline__ float2 csub(float2 a, float2 b){ return make_float2(a.x-b.x, a.y-b.y); }
__device__ __forceinline__ float2 cmul(float2 a, float2 b){ return make_float2(a.x*b.x - a.y*b.y, a.x*b.y + a.y*b.x); }
// conj(t)*x
__device__ __forceinline__ float2 cmulc(float2 t, float2 x){ return make_float2(t.x*x.x + t.y*x.y, t.x*x.y - t.y*x.x); }
__device__ __forceinline__ float2 conjf2(float2 a){ return make_float2(a.x, -a.y); }

__device__ __forceinline__ int rev5(int l){ return (int)(__brev((unsigned)l) >> 27); }
__device__ __forceinline__ int rev3c(int r){ return ((r&1)<<2) | (r&2) | ((r&4)>>2); }
__device__ __forceinline__ int sigma(int m){ return rev3c(m>>5) + 8*rev5(m&31); }

__device__ __forceinline__ float2 shflx(float2 v, int d){
    v.x = __shfl_xor_sync(0xffffffffu, v.x, d);
    v.y = __shfl_xor_sync(0xffffffffu, v.y, d);
    return v;
}

// ---------------- per-lane twiddle constants (computed once per kernel) ----------------
struct Tw { float2 base, t16, t8, t4, t2; };
__device__ __forceinline__ Tw make_tw(int l){
    Tw T; float s, c;
    __sincosf(-(TWO_PI/256.0f)*(float)l,  &s,&c); T.base = make_float2(c,s);
    __sincosf(-(PI_F/16.0f)*(float)(l&15),&s,&c); T.t16  = make_float2(c,s);
    __sincosf(-(PI_F/ 8.0f)*(float)(l&7), &s,&c); T.t8   = make_float2(c,s);
    __sincosf(-(PI_F/ 4.0f)*(float)(l&3), &s,&c); T.t4   = make_float2(c,s);
    __sincosf(-(PI_F/ 2.0f)*(float)(l&1), &s,&c); T.t2   = make_float2(c,s);
    return T;
}

#define RC8 0.70710678118654752440f

// DIF-8 in registers: natural in, bitrev3 out (reg r holds bin rev3(r))
__device__ __forceinline__ void fft8(float2 v[8]){
    float2 t0=cadd(v[0],v[4]), t1=cadd(v[1],v[5]), t2=cadd(v[2],v[6]), t3=cadd(v[3],v[7]);
    float2 u0=csub(v[0],v[4]);
    float2 d1=csub(v[1],v[5]); float2 u1=make_float2(RC8*(d1.x+d1.y), RC8*(d1.y-d1.x));
    float2 d2=csub(v[2],v[6]); float2 u2=make_float2(d2.y, -d2.x);
    float2 d3=csub(v[3],v[7]); float2 u3=make_float2(RC8*(d3.y-d3.x), -RC8*(d3.x+d3.y));
    float2 a0=cadd(t0,t2), a1=cadd(t1,t3), a2=csub(t0,t2);
    float2 dt=csub(t1,t3); float2 a3=make_float2(dt.y,-dt.x);
    float2 b0=cadd(u0,u2), b1=cadd(u1,u3), b2=csub(u0,u2);
    float2 du=csub(u1,u3); float2 b3=make_float2(du.y,-du.x);
    v[0]=cadd(a0,a1); v[1]=csub(a0,a1); v[2]=cadd(a2,a3); v[3]=csub(a2,a3);
    v[4]=cadd(b0,b1); v[5]=csub(b0,b1); v[6]=cadd(b2,b3); v[7]=csub(b2,b3);
}

// DIT-8 in registers: bitrev3 in, natural out, e^{+} (unnormalized inverse)
__device__ __forceinline__ void ifft8(float2 v[8]){
    float2 s0=cadd(v[0],v[1]), d0=csub(v[0],v[1]);
    float2 s1=cadd(v[2],v[3]), d1=csub(v[2],v[3]);
    float2 s2=cadd(v[4],v[5]), d2=csub(v[4],v[5]);
    float2 s3=cadd(v[6],v[7]), d3=csub(v[6],v[7]);
    float2 id1=make_float2(-d1.y,d1.x), id3=make_float2(-d3.y,d3.x);
    float2 p0=cadd(s0,s1), p2=csub(s0,s1), p1=cadd(d0,id1), p3=csub(d0,id1);
    float2 q0=cadd(s2,s3), q2=csub(s2,s3), q1=cadd(d2,id3), q3=csub(d2,id3);
    float2 w1q=make_float2(RC8*(q1.x-q1.y), RC8*(q1.x+q1.y));
    float2 iq2=make_float2(-q2.y,q2.x);
    float2 w3q=make_float2(-RC8*(q3.x+q3.y), RC8*(q3.x-q3.y));
    v[0]=cadd(p0,q0);  v[4]=csub(p0,q0);
    v[1]=cadd(p1,w1q); v[5]=csub(p1,w1q);
    v[2]=cadd(p2,iq2); v[6]=csub(p2,iq2);
    v[3]=cadd(p3,w3q); v[7]=csub(p3,w3q);
}

// v[r] *= base^{rev3(r)}  (chain in bin order 0,4,2,6,1,5,3,7)
__device__ __forceinline__ void twchain(float2 v[8], float2 base){
    float2 w = base;
    v[4]=cmul(v[4],w); w=cmul(w,base);
    v[2]=cmul(v[2],w); w=cmul(w,base);
    v[6]=cmul(v[6],w); w=cmul(w,base);
    v[1]=cmul(v[1],w); w=cmul(w,base);
    v[5]=cmul(v[5],w); w=cmul(w,base);
    v[3]=cmul(v[3],w); w=cmul(w,base);
    v[7]=cmul(v[7],w);
}

// DIF cross-lane stage, distance D, tD = e^{-i*pi*(l&(D-1))/D}
__device__ __forceinline__ void dif_stage(float2 v[8], int D, float2 tD, int lane){
    bool hi = (lane & D) != 0;
    #pragma unroll
    for (int k = 0; k < 8; k++){
        float2 p = shflx(v[k], D);
        v[k] = hi ? cmul(tD, csub(p, v[k])) : cadd(v[k], p);
    }
}
__device__ __forceinline__ void dif_stage1(float2 v[8], int lane){
    bool hi = (lane & 1) != 0;
    #pragma unroll
    for (int k = 0; k < 8; k++){
        float2 p = shflx(v[k], 1);
        v[k] = hi ? csub(p, v[k]) : cadd(v[k], p);
    }
}
// DIT cross-lane stage (inverse): w = conj(tD)
__device__ __forceinline__ void dit_stage(float2 v[8], int D, float2 tD, int lane){
    bool hi = (lane & D) != 0;
    #pragma unroll
    for (int k = 0; k < 8; k++){
        float2 p = shflx(v[k], D);
        v[k] = hi ? csub(p, cmulc(tD, v[k])) : cadd(v[k], cmulc(tD, p));
    }
}
__device__ __forceinline__ void dit_stage1(float2 v[8], int lane){
    bool hi = (lane & 1) != 0;
    #pragma unroll
    for (int k = 0; k < 8; k++){
        float2 p = shflx(v[k], 1);
        v[k] = hi ? csub(p, v[k]) : cadd(v[k], p);
    }
}

// forward 256: in v[r]=x[lane+32r] natural; out v[r]=X[rev3(r)+8*rev5(lane)]
__device__ __forceinline__ void fwd256(float2 v[8], const Tw& T, int lane){
    fft8(v);
    twchain(v, T.base);
    dif_stage(v, 16, T.t16, lane);
    dif_stage(v,  8, T.t8,  lane);
    dif_stage(v,  4, T.t4,  lane);
    dif_stage(v,  2, T.t2,  lane);
    dif_stage1(v, lane);
}
// inverse 256 (unnormalized): consumes fwd's layout, produces natural
__device__ __forceinline__ void inv256(float2 v[8], const Tw& T, int lane){
    dit_stage1(v, lane);
    dit_stage(v,  2, T.t2,  lane);
    dit_stage(v,  4, T.t4,  lane);
    dit_stage(v,  8, T.t8,  lane);
    dit_stage(v, 16, T.t16, lane);
    twchain(v, conjf2(T.base));
    ifft8(v);
}

// ---------------- setup ----------------
__global__ void k_setup(const float* __restrict__ shifts,
                        const int*   __restrict__ crop,
                        const void*  __restrict__ idxraw){
    if (threadIdx.x == 0){
        const int* w = (const int*)idxraw;
        int orr = 0;
        for (int k = 1; k < NB_; k += 2) orr |= w[k];
        bool is64 = (orr == 0);
        for (int b = 0; b < NB_; b++){
            int id = is64 ? (int)(((const long long*)idxraw)[b]) : w[b];
            g_cy[b] = crop[2*id];
            g_cx[b] = crop[2*id + 1];
            g_sy[b] = shifts[2*id];
            g_sx[b] = shifts[2*id + 1];
        }
    }
}

__global__ void k_setup_H(const float* __restrict__ Hr, const float* __restrict__ Hi){
    int idx = blockIdx.x*256 + threadIdx.x;     // 65536
    int my = idx & 255, mx = idx >> 8;
    int ky = sigma(my), kx = sigma(mx);
    size_t hsrc = (size_t)ky*N_ + kx;
    g_Ht[(size_t)mx*N_ + my] = make_float2(Hr[hsrc]*(1.0f/256.0f), Hi[hsrc]*(1.0f/256.0f));
}

// ---------------- probe fft2: rows then cols ----------------
__global__ void k_probe_rows(const float* __restrict__ pr, const float* __restrict__ pi){
    int blk = blockIdx.x, rb = blk & 31, p = blk >> 5;
    int w = threadIdx.x >> 5, l = threadIdx.x & 31;
    int y = rb*8 + w;
    Tw T = make_tw(l);
    size_t base = ((size_t)p*N_ + y)*N_;
    float2 v[8];
    #pragma unroll
    for (int r = 0; r < 8; r++){ int x = l + 32*r; v[r] = make_float2(pr[base+x], pi[base+x]); }
    fwd256(v, T, l);
    #pragma unroll
    for (int r = 0; r < 8; r++) g_probeF[base + l + 32*r] = v[r];
}

__global__ void k_probe_cols(){
    __shared__ float2 tile[2048];
    int blk = blockIdx.x, t = blk & 31, p = blk >> 5;
    int xg0 = t*8;
    int w = threadIdx.x >> 5, l = threadIdx.x & 31;
    Tw T = make_tw(l);
    float2* F = g_probeF + (size_t)p*NF;
    #pragma unroll
    for (int c = 0; c < 8; c++){
        int e = threadIdx.x + 256*c; int j = e & 7, my = e >> 3;
        tile[TADDR(my,j)] = F[(size_t)my*N_ + xg0 + j];
    }
    __syncthreads();
    float2 v[8];
    #pragma unroll
    for (int r = 0; r < 8; r++) v[r] = tile[TADDR(l+32*r, w)];
    fwd256(v, T, l);
    #pragma unroll
    for (int r = 0; r < 8; r++) tile[TADDR(l+32*r, w)] = v[r];
    __syncthreads();
    #pragma unroll
    for (int c = 0; c < 8; c++){
        int e = threadIdx.x + 256*c; int j = e & 7, my = e >> 3;
        F[(size_t)my*N_ + xg0 + j] = tile[TADDR(my,j)];
    }
}

// ---------------- shifted probes: ramp (full) + row inverse ----------------
__global__ void k_probes_rows(){
    int blk = blockIdx.x, rb = blk & 31, bp = blk >> 5;
    int p = bp & 7, b = bp >> 3;
    int w = threadIdx.x >> 5, l = threadIdx.x & 31;
    int my = rb*8 + w;
    Tw T = make_tw(l);
    float sy = g_sy[b], sx = g_sx[b];
    int ky = sigma(my);
    // C = e^{-2pi i (sy*ky/256 + sx*rev5(l)/32)} / 256 (range-reduced)
    float f = sy*(float)ky*(1.0f/256.0f) + sx*(float)rev5(l)*(1.0f/32.0f);
    f -= rintf(f);
    float s, c; __sincosf(-TWO_PI*f, &s, &c);
    float2 C = make_float2(c*(1.0f/256.0f), s*(1.0f/256.0f));
    float fb = sx*(1.0f/256.0f); fb -= rintf(fb);
    __sincosf(-TWO_PI*fb, &s, &c); float2 B = make_float2(c, s);
    size_t base = ((size_t)p*N_ + my)*N_;
    float2 v[8];
    #pragma unroll
    for (int r = 0; r < 8; r++) v[r] = g_probeF[base + l + 32*r];
    // apply C * B^{rev3(r)}
    float2 wv = C;
    v[0]=cmul(v[0],wv); wv=cmul(wv,B);
    v[4]=cmul(v[4],wv); wv=cmul(wv,B);
    v[2]=cmul(v[2],wv); wv=cmul(wv,B);
    v[6]=cmul(v[6],wv); wv=cmul(wv,B);
    v[1]=cmul(v[1],wv); wv=cmul(wv,B);
    v[5]=cmul(v[5],wv); wv=cmul(wv,B);
    v[3]=cmul(v[3],wv); wv=cmul(wv,B);
    v[7]=cmul(v[7],wv);
    inv256(v, T, l);
    float2* dst = g_probes + ((size_t)b*P_ + p)*NF + (size_t)my*N_;
    #pragma unroll
    for (int r = 0; r < 8; r++) dst[l + 32*r] = v[r];
}

// ---------------- shifted probes: col inverse (scaled 1/256) ----------------
__global__ void k_probes_cols(){
    __shared__ float2 tile[2048];
    int blk = blockIdx.x, t = blk & 31, f = blk >> 5;
    int xg0 = t*8;
    int w = threadIdx.x >> 5, l = threadIdx.x & 31;
    Tw T = make_tw(l);
    float2* F = g_probes + (size_t)f*NF;
    #pragma unroll
    for (int c = 0; c < 8; c++){
        int e = threadIdx.x + 256*c; int j = e & 7, my = e >> 3;
        tile[TADDR(my,j)] = F[(size_t)my*N_ + xg0 + j];
    }
    __syncthreads();
    float2 v[8];
    #pragma unroll
    for (int r = 0; r < 8; r++) v[r] = tile[TADDR(l+32*r, w)];
    inv256(v, T, l);
    #pragma unroll
    for (int r = 0; r < 8; r++){
        v[r].x *= (1.0f/256.0f); v[r].y *= (1.0f/256.0f);
        tile[TADDR(l+32*r, w)] = v[r];
    }
    __syncthreads();
    #pragma unroll
    for (int c = 0; c < 8; c++){
        int e = threadIdx.x + 256*c; int j = e & 7, my = e >> 3;
        F[(size_t)my*N_ + xg0 + j] = tile[TADDR(my,j)];
    }
}

// ---------------- rows pass A: [row-inv] -> x obj -> row-fwd, writes pp ----------------
__global__ void k_rows_A(const float* __restrict__ obja, const float* __restrict__ objp,
                         float* __restrict__ pp_out, int z){
    int blk = blockIdx.x, rb = blk & 31, bo = blk >> 5;
    int o = bo & 1, b = bo >> 1;
    int w = threadIdx.x >> 5, l = threadIdx.x & 31;
    int y = rb*8 + w;
    Tw T = make_tw(l);
    int cy = g_cy[b], cx = g_cx[b];
    size_t obase = ((size_t)(o*Z_ + z)*OY_ + (size_t)(cy + y))*OY_ + cx;
    float scale = (z == 0) ? 1.0f : (1.0f/256.0f);
    size_t ppbase = ((((size_t)b*O_ + o)*Z_ + z)*N_ + y)*(size_t)N_;
    float2 obj[8];
    #pragma unroll
    for (int r = 0; r < 8; r++){
        int x = l + 32*r;
        float A = obja[obase + x], ph = objp[obase + x];
        float sn, cs; __sincosf(ph, &sn, &cs);
        obj[r] = make_float2(A*cs*scale, A*sn*scale);
        pp_out[ppbase + x] = ph;
    }
    for (int p = 0; p < P_; p++){
        const float2* src = (z == 0)
            ? g_probes + ((size_t)b*P_ + p)*NF + (size_t)y*N_
            : g_bufB  + ((size_t)bo*P_ + p)*NF + (size_t)y*N_;
        float2 v[8];
        #pragma unroll
        for (int r = 0; r < 8; r++) v[r] = src[l + 32*r];
        if (z) inv256(v, T, l);
        #pragma unroll
        for (int r = 0; r < 8; r++) v[r] = cmul(v[r], obj[r]);
        fwd256(v, T, l);
        float2* dst = g_bufA + ((size_t)bo*P_ + p)*NF + (size_t)y*N_;
        #pragma unroll
        for (int r = 0; r < 8; r++) dst[l + 32*r] = v[r];
    }
}

// ---------------- cols pass B: col-fwd -> x Ht -> col-inv ----------------
__global__ void k_cols_H(){
    __shared__ float2 tile[2048];
    int blk = blockIdx.x, t = blk & 31, f = blk >> 5;
    int xg0 = t*8;
    int w = threadIdx.x >> 5, l = threadIdx.x & 31;
    Tw T = make_tw(l);
    const float2* s = g_bufA + (size_t)f*NF;
    #pragma unroll
    for (int c = 0; c < 8; c++){
        int e = threadIdx.x + 256*c; int j = e & 7, my = e >> 3;
        tile[TADDR(my,j)] = s[(size_t)my*N_ + xg0 + j];
    }
    __syncthreads();
    float2 v[8];
    #pragma unroll
    for (int r = 0; r < 8; r++) v[r] = tile[TADDR(l+32*r, w)];
    fwd256(v, T, l);
    const float2* Hc = g_Ht + (size_t)(xg0 + w)*N_;
    #pragma unroll
    for (int r = 0; r < 8; r++) v[r] = cmul(v[r], Hc[l + 32*r]);
    inv256(v, T, l);
    #pragma unroll
    for (int r = 0; r < 8; r++) tile[TADDR(l+32*r, w)] = v[r];
    __syncthreads();
    float2* d = g_bufB + (size_t)f*NF;
    #pragma unroll
    for (int c = 0; c < 8; c++){
        int e = threadIdx.x + 256*c; int j = e & 7, my = e >> 3;
        d[(size_t)my*N_ + xg0 + j] = tile[TADDR(my,j)];
    }
}

// ---------------- final: col-fwd -> weighted |.|^2 -> dp (fftshift scatter) ----------------
__global__ void k_cols_final(const float* __restrict__ occu, float* __restrict__ dp){
    __shared__ float2 tile[2048];
    int blk = blockIdx.x, t = blk & 31, b = blk >> 5;
    int xg0 = t*8;
    int w = threadIdx.x >> 5, l = threadIdx.x & 31;
    Tw T = make_tw(l);
    float acc[8];
    #pragma unroll
    for (int k = 0; k < 8; k++) acc[k] = 0.0f;
    for (int o = 0; o < O_; o++){
        float wt = occu[o];
        for (int p = 0; p < P_; p++){
            const float2* s = g_bufA + ((size_t)((b*O_ + o)*P_ + p))*NF;
            __syncthreads();
            #pragma unroll
            for (int c = 0; c < 8; c++){
                int e = threadIdx.x + 256*c; int j = e & 7, my = e >> 3;
                tile[TADDR(my,j)] = s[(size_t)my*N_ + xg0 + j];
            }
            __syncthreads();
            float2 v[8];
            #pragma unroll
            for (int r = 0; r < 8; r++) v[r] = tile[TADDR(l+32*r, w)];
            fwd256(v, T, l);
            #pragma unroll
            for (int r = 0; r < 8; r++) acc[r] += wt*(v[r].x*v[r].x + v[r].y*v[r].y);
        }
    }
    int kx = sigma(xg0 + w);
    int xs = (kx + 128) & 255;
    int r5 = rev5(l);
    #pragma unroll
    for (int r = 0; r < 8; r++){
        int ky = rev3c(r) + 8*r5;
        dp[(size_t)b*NF + (size_t)((ky + 128) & 255)*N_ + xs] = acc[r];
    }
}

// ---------------- launch ----------------
extern "C" void kernel_launch(void* const* d_in, const int* in_sizes, int n_in,
                              void* d_out, int out_size){
    const float* obja   = (const float*)d_in[0];
    const float* objp   = (const float*)d_in[1];
    const float* pr     = (const float*)d_in[2];
    const float* pi     = (const float*)d_in[3];
    const float* Hr     = (const float*)d_in[4];
    const float* Hi     = (const float*)d_in[5];
    const float* occu   = (const float*)d_in[6];
    const float* shifts = (const float*)d_in[7];
    const int*   crop   = (const int*)d_in[8];
    const void*  idx    = d_in[9];

    float* dp = (float*)d_out;                    // (NB, 256, 256)
    float* pp = dp + (size_t)NB_ * NF;            // (NB, O, Z, 256, 256)

    k_setup<<<1, 32>>>(shifts, crop, idx);
    k_setup_H<<<256, 256>>>(Hr, Hi);
    k_probe_rows<<<P_*32, 256>>>(pr, pi);
    k_probe_cols<<<P_*32, 256>>>();
    k_probes_rows<<<NB_*P_*32, 256>>>();
    k_probes_cols<<<NB_*P_*32, 256>>>();

    k_rows_A<<<NB_*O_*32, 256>>>(obja, objp, pp, 0);
    for (int z = 0; z < Z_ - 1; z++){
        k_cols_H<<<NB_*O_*P_*32, 256>>>();
        k_rows_A<<<NB_*O_*32, 256>>>(obja, objp, pp, z + 1);
    }
    k_cols_final<<<NB_*32, 256>>>(occu, dp);
}

// round 7
// speedup vs baseline: 2.7828x; 1.1645x over previous
#include <cuda_runtime.h>

// ---------------- problem constants ----------------
#define O_    2
#define Z_    8
#define OY_   1024
#define P_    8
#define N_    256
#define NB_   32
#define NF    65536
#define TWO_PI 6.28318530717958647692f
#define PI_F  3.14159265358979323846f

// XOR-swizzled column-tile addressing (8 columns x 256 rows, float2).
#define TADDR(my,j) ((((my) << 3)) | ((j) ^ (((my) >> 2) & 7)))

// ---------------- static device scratch ----------------
__device__ int    g_cy[NB_], g_cx[NB_];
__device__ float  g_sy[NB_], g_sx[NB_];
__device__ float2 g_Ht[(size_t)NF];                                   // H permuted both axes, /256 folded
__device__ __align__(16) float2 g_probeF[(size_t)P_ * NF];            // fft2(probe), permuted axes
__device__ __align__(16) float2 g_probes[(size_t)NB_ * P_ * NF];      // shifted probes (spatial)
__device__ __align__(16) float2 g_bufA[(size_t)NB_ * O_ * P_ * NF];
__device__ __align__(16) float2 g_bufB[(size_t)NB_ * O_ * P_ * NF];

// ---------------- complex helpers ----------------
__device__ __forceinline__ float2 cadd(float2 a, float2 b){ return make_float2(a.x+b.x, a.y+b.y); }
__device__ __forceinline__ float2 csub(float2 a, float2 b){ return make_float2(a.x-b.x, a.y-b.y); }
__device__ __forceinline__ float2 cmul(float2 a, float2 b){ return make_float2(a.x*b.x - a.y*b.y, a.x*b.y + a.y*b.x); }
// conj(t)*x
__device__ __forceinline__ float2 cmulc(float2 t, float2 x){ return make_float2(t.x*x.x + t.y*x.y, t.x*x.y - t.y*x.x); }
__device__ __forceinline__ float2 conjf2(float2 a){ return make_float2(a.x, -a.y); }

__device__ __forceinline__ int rev5(int l){ return (int)(__brev((unsigned)l) >> 27); }
__device__ __forceinline__ int rev3c(int r){ return ((r&1)<<2) | (r&2) | ((r&4)>>2); }
// y-axis frequency permutation at row position m (unchanged storage)
__device__ __forceinline__ int sigma(int m){ return rev3c(m>>5) + 8*rev5(m&31); }
// x-axis frequency permutation at PHYSICAL float2 index q (float4-packed storage):
// q = PHYS(l,r) = 2l + 64*(r>>1) + (r&1)  ->  kx = rev3(r) + 8*rev5(l)
__device__ __forceinline__ int sigx(int q){ return rev3c(2*(q>>6) + (q&1)) + 8*rev5((q>>1)&31); }

__device__ __forceinline__ float2 shflx(float2 v, int d){
    v.x = __shfl_xor_sync(0xffffffffu, v.x, d);
    v.y = __shfl_xor_sync(0xffffffffu, v.y, d);
    return v;
}

// ---------------- per-lane FFT constants (computed once per kernel) ----------------
// wD = (lane & D) ? e^{-i*pi*(l&(D-1))/D} : 1 ;  tD = (lane & D) ? -1 : +1
struct WF { float2 w16, w8, w4, w2, base; float t16, t8, t4, t2, t1; };
__device__ __forceinline__ WF make_wf(int l){
    WF W; float s, c;
    __sincosf(-(TWO_PI/256.0f)*(float)l, &s, &c); W.base = make_float2(c, s);
    __sincosf(-(PI_F/16.0f)*(float)(l&15), &s, &c); W.w16 = (l&16)? make_float2(c,s) : make_float2(1.f,0.f);
    __sincosf(-(PI_F/ 8.0f)*(float)(l& 7), &s, &c); W.w8  = (l& 8)? make_float2(c,s) : make_float2(1.f,0.f);
    __sincosf(-(PI_F/ 4.0f)*(float)(l& 3), &s, &c); W.w4  = (l& 4)? make_float2(c,s) : make_float2(1.f,0.f);
    __sincosf(-(PI_F/ 2.0f)*(float)(l& 1), &s, &c); W.w2  = (l& 2)? make_float2(c,s) : make_float2(1.f,0.f);
    W.t16 = (l&16)? -1.f:1.f;  W.t8 = (l&8)? -1.f:1.f;  W.t4 = (l&4)? -1.f:1.f;
    W.t2  = (l& 2)? -1.f:1.f;  W.t1 = (l&1)? -1.f:1.f;
    return W;
}

#define RC8 0.70710678118654752440f

// DIF-8 in registers: natural in, bitrev3 out (reg r holds bin rev3(r))
__device__ __forceinline__ void fft8(float2 v[8]){
    float2 t0=cadd(v[0],v[4]), t1=cadd(v[1],v[5]), t2=cadd(v[2],v[6]), t3=cadd(v[3],v[7]);
    float2 u0=csub(v[0],v[4]);
    float2 d1=csub(v[1],v[5]); float2 u1=make_float2(RC8*(d1.x+d1.y), RC8*(d1.y-d1.x));
    float2 d2=csub(v[2],v[6]); float2 u2=make_float2(d2.y, -d2.x);
    float2 d3=csub(v[3],v[7]); float2 u3=make_float2(RC8*(d3.y-d3.x), -RC8*(d3.x+d3.y));
    float2 a0=cadd(t0,t2), a1=cadd(t1,t3), a2=csub(t0,t2);
    float2 dt=csub(t1,t3); float2 a3=make_float2(dt.y,-dt.x);
    float2 b0=cadd(u0,u2), b1=cadd(u1,u3), b2=csub(u0,u2);
    float2 du=csub(u1,u3); float2 b3=make_float2(du.y,-du.x);
    v[0]=cadd(a0,a1); v[1]=csub(a0,a1); v[2]=cadd(a2,a3); v[3]=csub(a2,a3);
    v[4]=cadd(b0,b1); v[5]=csub(b0,b1); v[6]=cadd(b2,b3); v[7]=csub(b2,b3);
}

// DIT-8 in registers: bitrev3 in, natural out, e^{+} (unnormalized inverse)
__device__ __forceinline__ void ifft8(float2 v[8]){
    float2 s0=cadd(v[0],v[1]), d0=csub(v[0],v[1]);
    float2 s1=cadd(v[2],v[3]), d1=csub(v[2],v[3]);
    float2 s2=cadd(v[4],v[5]), d2=csub(v[4],v[5]);
    float2 s3=cadd(v[6],v[7]), d3=csub(v[6],v[7]);
    float2 id1=make_float2(-d1.y,d1.x), id3=make_float2(-d3.y,d3.x);
    float2 p0=cadd(s0,s1), p2=csub(s0,s1), p1=cadd(d0,id1), p3=csub(d0,id1);
    float2 q0=cadd(s2,s3), q2=csub(s2,s3), q1=cadd(d2,id3), q3=csub(d2,id3);
    float2 w1q=make_float2(RC8*(q1.x-q1.y), RC8*(q1.x+q1.y));
    float2 iq2=make_float2(-q2.y,q2.x);
    float2 w3q=make_float2(-RC8*(q3.x+q3.y), RC8*(q3.x-q3.y));
    v[0]=cadd(p0,q0);  v[4]=csub(p0,q0);
    v[1]=cadd(p1,w1q); v[5]=csub(p1,w1q);
    v[2]=cadd(p2,iq2); v[6]=csub(p2,iq2);
    v[3]=cadd(p3,w3q); v[7]=csub(p3,w3q);
}

// v[r] *= base^{rev3(r)}  (chain in bin order 0,4,2,6,1,5,3,7)
__device__ __forceinline__ void twchain(float2 v[8], float2 base){
    float2 w = base;
    v[4]=cmul(v[4],w); w=cmul(w,base);
    v[2]=cmul(v[2],w); w=cmul(w,base);
    v[6]=cmul(v[6],w); w=cmul(w,base);
    v[1]=cmul(v[1],w); w=cmul(w,base);
    v[5]=cmul(v[5],w); w=cmul(w,base);
    v[3]=cmul(v[3],w); w=cmul(w,base);
    v[7]=cmul(v[7],w);
}

// ---- select-free cross-lane stages ----
// forward (DIF): u = p + t*v ; v = w*u     (lo: v+p ; hi: tD*(p-v))
__device__ __forceinline__ void fstage(float2 v[8], int D, float2 w, float t){
    #pragma unroll
    for (int k = 0; k < 8; k++){
        float2 p = shflx(v[k], D);
        float2 u = make_float2(fmaf(t, v[k].x, p.x), fmaf(t, v[k].y, p.y));
        v[k] = cmul(w, u);
    }
}
__device__ __forceinline__ void fstage1(float2 v[8], float t){
    #pragma unroll
    for (int k = 0; k < 8; k++){
        float2 p = shflx(v[k], 1);
        v[k] = make_float2(fmaf(t, v[k].x, p.x), fmaf(t, v[k].y, p.y));
    }
}
// inverse (DIT): y = conj(w)*v ; v = shfl(y) + t*y   (lo: v + conj(tD)*p ; hi: p - conj(tD)*v)
__device__ __forceinline__ void istage(float2 v[8], int D, float2 w, float t){
    #pragma unroll
    for (int k = 0; k < 8; k++){
        float2 y = cmulc(w, v[k]);
        float2 p = shflx(y, D);
        v[k] = make_float2(fmaf(t, y.x, p.x), fmaf(t, y.y, p.y));
    }
}
__device__ __forceinline__ void istage1(float2 v[8], float t){
    #pragma unroll
    for (int k = 0; k < 8; k++){
        float2 p = shflx(v[k], 1);
        v[k] = make_float2(fmaf(t, v[k].x, p.x), fmaf(t, v[k].y, p.y));
    }
}

// forward 256: in v[r]=x[lane+32r] natural; out v[r]=X[rev3(r)+8*rev5(lane)]
__device__ __forceinline__ void fwd256(float2 v[8], const WF& W){
    fft8(v);
    twchain(v, W.base);
    fstage(v,16,W.w16,W.t16);
    fstage(v, 8,W.w8 ,W.t8 );
    fstage(v, 4,W.w4 ,W.t4 );
    fstage(v, 2,W.w2 ,W.t2 );
    fstage1(v, W.t1);
}
// inverse 256 (unnormalized): consumes fwd's layout, produces natural
__device__ __forceinline__ void inv256(float2 v[8], const WF& W){
    istage1(v, W.t1);
    istage(v, 2,W.w2 ,W.t2 );
    istage(v, 4,W.w4 ,W.t4 );
    istage(v, 8,W.w8 ,W.t8 );
    istage(v,16,W.w16,W.t16);
    twchain(v, conjf2(W.base));
    ifft8(v);
}

// ---- float4-packed row I/O: slot l+32*rp holds (v[2rp], v[2rp+1]) ----
__device__ __forceinline__ void load8(float2 v[8], const float2* row, int l){
    const float4* r4 = (const float4*)row;
    #pragma unroll
    for (int rp = 0; rp < 4; rp++){
        float4 q = r4[l + 32*rp];
        v[2*rp]   = make_float2(q.x, q.y);
        v[2*rp+1] = make_float2(q.z, q.w);
    }
}
__device__ __forceinline__ void store8(float2* row, const float2 v[8], int l){
    float4* r4 = (float4*)row;
    #pragma unroll
    for (int rp = 0; rp < 4; rp++)
        r4[l + 32*rp] = make_float4(v[2*rp].x, v[2*rp].y, v[2*rp+1].x, v[2*rp+1].y);
}

// ---------------- setup ----------------
__global__ void k_setup(const float* __restrict__ shifts,
                        const int*   __restrict__ crop,
                        const void*  __restrict__ idxraw){
    if (threadIdx.x == 0){
        const int* w = (const int*)idxraw;
        int orr = 0;
        for (int k = 1; k < NB_; k += 2) orr |= w[k];
        bool is64 = (orr == 0);
        for (int b = 0; b < NB_; b++){
            int id = is64 ? (int)(((const long long*)idxraw)[b]) : w[b];
            g_cy[b] = crop[2*id];
            g_cx[b] = crop[2*id + 1];
            g_sy[b] = shifts[2*id];
            g_sx[b] = shifts[2*id + 1];
        }
    }
}

__global__ void k_setup_H(const float* __restrict__ Hr, const float* __restrict__ Hi){
    int idx = blockIdx.x*256 + threadIdx.x;     // 65536
    int my = idx & 255, mx = idx >> 8;
    int ky = sigma(my), kx = sigx(mx);
    size_t hsrc = (size_t)ky*N_ + kx;
    g_Ht[(size_t)mx*N_ + my] = make_float2(Hr[hsrc]*(1.0f/256.0f), Hi[hsrc]*(1.0f/256.0f));
}

// ---------------- probe fft2 ----------------
__global__ void k_probe_rows(const float* __restrict__ pr, const float* __restrict__ pi){
    int blk = blockIdx.x, rb = blk & 31, p = blk >> 5;
    int w = threadIdx.x >> 5, l = threadIdx.x & 31;
    int y = rb*8 + w;
    WF W = make_wf(l);
    size_t base = ((size_t)p*N_ + y)*N_;
    float2 v[8];
    #pragma unroll
    for (int r = 0; r < 8; r++){ int x = l + 32*r; v[r] = make_float2(pr[base+x], pi[base+x]); }
    fwd256(v, W);
    store8(g_probeF + base, v, l);
}

__global__ void k_probe_cols(){
    __shared__ float2 tile[2048];
    int blk = blockIdx.x, t = blk & 31, p = blk >> 5;
    int xg0 = t*8;
    int w = threadIdx.x >> 5, l = threadIdx.x & 31;
    WF W = make_wf(l);
    float2* F = g_probeF + (size_t)p*NF;
    #pragma unroll
    for (int c = 0; c < 8; c++){
        int e = threadIdx.x + 256*c; int j = e & 7, my = e >> 3;
        tile[TADDR(my,j)] = F[(size_t)my*N_ + xg0 + j];
    }
    __syncthreads();
    float2 v[8];
    #pragma unroll
    for (int r = 0; r < 8; r++) v[r] = tile[TADDR(l+32*r, w)];
    fwd256(v, W);
    #pragma unroll
    for (int r = 0; r < 8; r++) tile[TADDR(l+32*r, w)] = v[r];
    __syncthreads();
    #pragma unroll
    for (int c = 0; c < 8; c++){
        int e = threadIdx.x + 256*c; int j = e & 7, my = e >> 3;
        F[(size_t)my*N_ + xg0 + j] = tile[TADDR(my,j)];
    }
}

// ---------------- shifted probes ----------------
__global__ void k_probes_rows(){
    int blk = blockIdx.x, rb = blk & 31, bp = blk >> 5;
    int p = bp & 7, b = bp >> 3;
    int w = threadIdx.x >> 5, l = threadIdx.x & 31;
    int my = rb*8 + w;
    WF W = make_wf(l);
    float sy = g_sy[b], sx = g_sx[b];
    int ky = sigma(my);
    float f = sy*(float)ky*(1.0f/256.0f) + sx*(float)rev5(l)*(1.0f/32.0f);
    f -= rintf(f);
    float s, c; __sincosf(-TWO_PI*f, &s, &c);
    float2 C = make_float2(c*(1.0f/256.0f), s*(1.0f/256.0f));
    float fb = sx*(1.0f/256.0f); fb -= rintf(fb);
    __sincosf(-TWO_PI*fb, &s, &c); float2 B = make_float2(c, s);
    size_t base = ((size_t)p*N_ + my)*N_;
    float2 v[8];
    load8(v, g_probeF + base, l);
    float2 wv = C;
    v[0]=cmul(v[0],wv); wv=cmul(wv,B);
    v[4]=cmul(v[4],wv); wv=cmul(wv,B);
    v[2]=cmul(v[2],wv); wv=cmul(wv,B);
    v[6]=cmul(v[6],wv); wv=cmul(wv,B);
    v[1]=cmul(v[1],wv); wv=cmul(wv,B);
    v[5]=cmul(v[5],wv); wv=cmul(wv,B);
    v[3]=cmul(v[3],wv); wv=cmul(wv,B);
    v[7]=cmul(v[7],wv);
    inv256(v, W);
    store8(g_probes + ((size_t)b*P_ + p)*NF + (size_t)my*N_, v, l);
}

__global__ void k_probes_cols(){
    __shared__ float2 tile[2048];
    int blk = blockIdx.x, t = blk & 31, f = blk >> 5;
    int xg0 = t*8;
    int w = threadIdx.x >> 5, l = threadIdx.x & 31;
    WF W = make_wf(l);
    float2* F = g_probes + (size_t)f*NF;
    #pragma unroll
    for (int c = 0; c < 8; c++){
        int e = threadIdx.x + 256*c; int j = e & 7, my = e >> 3;
        tile[TADDR(my,j)] = F[(size_t)my*N_ + xg0 + j];
    }
    __syncthreads();
    float2 v[8];
    #pragma unroll
    for (int r = 0; r < 8; r++) v[r] = tile[TADDR(l+32*r, w)];
    inv256(v, W);
    #pragma unroll
    for (int r = 0; r < 8; r++){
        v[r].x *= (1.0f/256.0f); v[r].y *= (1.0f/256.0f);
        tile[TADDR(l+32*r, w)] = v[r];
    }
    __syncthreads();
    #pragma unroll
    for (int c = 0; c < 8; c++){
        int e = threadIdx.x + 256*c; int j = e & 7, my = e >> 3;
        F[(size_t)my*N_ + xg0 + j] = tile[TADDR(my,j)];
    }
}

// ---------------- rows pass A ----------------
__global__ void k_rows_A(const float* __restrict__ obja, const float* __restrict__ objp,
                         float* __restrict__ pp_out, int z){
    int blk = blockIdx.x, rb = blk & 31, bo = blk >> 5;
    int o = bo & 1, b = bo >> 1;
    int w = threadIdx.x >> 5, l = threadIdx.x & 31;
    int y = rb*8 + w;
    WF W = make_wf(l);
    int cy = g_cy[b], cx = g_cx[b];
    size_t obase = ((size_t)(o*Z_ + z)*OY_ + (size_t)(cy + y))*OY_ + cx;
    float scale = (z == 0) ? 1.0f : (1.0f/256.0f);
    size_t ppbase = ((((size_t)b*O_ + o)*Z_ + z)*N_ + y)*(size_t)N_;
    float2 obj[8];
    #pragma unroll
    for (int r = 0; r < 8; r++){
        int x = l + 32*r;
        float A = obja[obase + x], ph = objp[obase + x];
        float sn, cs; __sincosf(ph, &sn, &cs);
        obj[r] = make_float2(A*cs*scale, A*sn*scale);
        pp_out[ppbase + x] = ph;
    }
    for (int p = 0; p < P_; p++){
        const float2* src = (z == 0)
            ? g_probes + ((size_t)b*P_ + p)*NF + (size_t)y*N_
            : g_bufB  + ((size_t)bo*P_ + p)*NF + (size_t)y*N_;
        float2 v[8];
        load8(v, src, l);
        if (z) inv256(v, W);
        #pragma unroll
        for (int r = 0; r < 8; r++) v[r] = cmul(v[r], obj[r]);
        fwd256(v, W);
        store8(g_bufA + ((size_t)bo*P_ + p)*NF + (size_t)y*N_, v, l);
    }
}

// ---------------- cols pass B ----------------
__global__ void k_cols_H(){
    __shared__ float2 tile[2048];
    int blk = blockIdx.x, t = blk & 31, f = blk >> 5;
    int xg0 = t*8;
    int w = threadIdx.x >> 5, l = threadIdx.x & 31;
    WF W = make_wf(l);
    const float2* s = g_bufA + (size_t)f*NF;
    #pragma unroll
    for (int c = 0; c < 8; c++){
        int e = threadIdx.x + 256*c; int j = e & 7, my = e >> 3;
        tile[TADDR(my,j)] = s[(size_t)my*N_ + xg0 + j];
    }
    __syncthreads();
    float2 v[8];
    #pragma unroll
    for (int r = 0; r < 8; r++) v[r] = tile[TADDR(l+32*r, w)];
    fwd256(v, W);
    const float2* Hc = g_Ht + (size_t)(xg0 + w)*N_;
    #pragma unroll
    for (int r = 0; r < 8; r++) v[r] = cmul(v[r], Hc[l + 32*r]);
    inv256(v, W);
    #pragma unroll
    for (int r = 0; r < 8; r++) tile[TADDR(l+32*r, w)] = v[r];
    __syncthreads();
    float2* d = g_bufB + (size_t)f*NF;
    #pragma unroll
    for (int c = 0; c < 8; c++){
        int e = threadIdx.x + 256*c; int j = e & 7, my = e >> 3;
        d[(size_t)my*N_ + xg0 + j] = tile[TADDR(my,j)];
    }
}

// ---------------- final ----------------
__global__ void k_cols_final(const float* __restrict__ occu, float* __restrict__ dp){
    __shared__ float2 tile[2048];
    int blk = blockIdx.x, t = blk & 31, b = blk >> 5;
    int xg0 = t*8;
    int w = threadIdx.x >> 5, l = threadIdx.x & 31;
    WF W = make_wf(l);
    float acc[8];
    #pragma unroll
    for (int k = 0; k < 8; k++) acc[k] = 0.0f;
    for (int o = 0; o < O_; o++){
        float wt = occu[o];
        for (int p = 0; p < P_; p++){
            const float2* s = g_bufA + ((size_t)((b*O_ + o)*P_ + p))*NF;
            __syncthreads();
            #pragma unroll
            for (int c = 0; c < 8; c++){
                int e = threadIdx.x + 256*c; int j = e & 7, my = e >> 3;
                tile[TADDR(my,j)] = s[(size_t)my*N_ + xg0 + j];
            }
            __syncthreads();
            float2 v[8];
            #pragma unroll
            for (int r = 0; r < 8; r++) v[r] = tile[TADDR(l+32*r, w)];
            fwd256(v, W);
            #pragma unroll
            for (int r = 0; r < 8; r++) acc[r] += wt*(v[r].x*v[r].x + v[r].y*v[r].y);
        }
    }
    int kx = sigx(xg0 + w);
    int xs = (kx + 128) & 255;
    int r5 = rev5(l);
    #pragma unroll
    for (int r = 0; r < 8; r++){
        int ky = rev3c(r) + 8*r5;
        dp[(size_t)b*NF + (size_t)((ky + 128) & 255)*N_ + xs] = acc[r];
    }
}

// ---------------- launch ----------------
extern "C" void kernel_launch(void* const* d_in, const int* in_sizes, int n_in,
                              void* d_out, int out_size){
    const float* obja   = (const float*)d_in[0];
    const float* objp   = (const float*)d_in[1];
    const float* pr     = (const float*)d_in[2];
    const float* pi     = (const float*)d_in[3];
    const float* Hr     = (const float*)d_in[4];
    const float* Hi     = (const float*)d_in[5];
    const float* occu   = (const float*)d_in[6];
    const float* shifts = (const float*)d_in[7];
    const int*   crop   = (const int*)d_in[8];
    const void*  idx    = d_in[9];

    float* dp = (float*)d_out;                    // (NB, 256, 256)
    float* pp = dp + (size_t)NB_ * NF;            // (NB, O, Z, 256, 256)

    k_setup<<<1, 32>>>(shifts, crop, idx);
    k_setup_H<<<256, 256>>>(Hr, Hi);
    k_probe_rows<<<P_*32, 256>>>(pr, pi);
    k_probe_cols<<<P_*32, 256>>>();
    k_probes_rows<<<NB_*P_*32, 256>>>();
    k_probes_cols<<<NB_*P_*32, 256>>>();

    k_rows_A<<<NB_*O_*32, 256>>>(obja, objp, pp, 0);
    for (int z = 0; z < Z_ - 1; z++){
        k_cols_H<<<NB_*O_*P_*32, 256>>>();
        k_rows_A<<<NB_*O_*32, 256>>>(obja, objp, pp, z + 1);
    }
    k_cols_final<<<NB_*32, 256>>>(occu, dp);
}